// round 16
// baseline (speedup 1.0000x reference)
#include <cuda_runtime.h>
#include <cuda_bf16.h>

// RGCN_317827579998 : 3-layer GraphConv, N=50000 nodes, E=800000 edges, D=128.
//
// R16: remove ALL global atomics (the ~4ms sink per R14/R15 accounting).
//   - k_hist:  148 blocks x 512thr; block owns ~338 nodes; streams the whole
//              src+dst arrays (int4, L2-resident) counting into smem; writes
//              indeg + in/out norms. No global atomics.
//   - k_scan:  unchanged proven single-block scan (indeg -> rowptr).
//   - k_fillb: 148 blocks; smem cursors init from rowptr; streams dst; on
//              range-match pos=smem_cursor++, g_csr[pos]=src[e]. No global
//              atomics.
//   GEMM-first layers (R15, passing, verbatim):
//     Y = X@W ; OUT = relu?( in_norm .* gather-sum(out_norm .* Y) + b )
// Launch order: hist(1), scan(2), gemm1(3), fillb(4) <- PROFILED,
//               agg1, gemm2, agg2, gemm3, agg3->out.

#define N_NODES 50000
#define N_EDGES 800000
#define D 128
#define DV (D / 4)   // float4s per row
#define E4 (N_EDGES / 4)

#define NBLK 148
#define RNODES 338   // 148*338 = 50024 >= N_NODES

// ---- device scratch (allocation-free rules -> __device__ globals) ----
__device__ int   g_indeg[N_NODES];
__device__ float g_outnorm[N_NODES];
__device__ float g_innorm[N_NODES];
__device__ int   g_rowptr[N_NODES + 1];
__device__ int   g_csr[N_EDGES];
__device__ float g_t[N_NODES * D];  // gemm output Y (gather source)
__device__ float g_h[N_NODES * D];  // layer output H (gemm input)

// ---------------------------------------------------------------------------
// Histogram + norms. Each block owns nodes [lo, lo+RNODES); streams all edges.
__global__ void __launch_bounds__(512)
k_hist(const int* __restrict__ src, const int* __restrict__ dst) {
    __shared__ int s_in[RNODES];
    __shared__ int s_out[RNODES];
    int lo = blockIdx.x * RNODES;

    for (int r = threadIdx.x; r < RNODES; r += blockDim.x) {
        s_in[r] = 0;
        s_out[r] = 0;
    }
    __syncthreads();

    const int4* s4 = (const int4*)src;
    const int4* d4 = (const int4*)dst;
    for (int i = threadIdx.x; i < E4; i += blockDim.x) {
        int4 s = s4[i];
        int r;
        r = s.x - lo; if ((unsigned)r < RNODES) atomicAdd(&s_out[r], 1);
        r = s.y - lo; if ((unsigned)r < RNODES) atomicAdd(&s_out[r], 1);
        r = s.z - lo; if ((unsigned)r < RNODES) atomicAdd(&s_out[r], 1);
        r = s.w - lo; if ((unsigned)r < RNODES) atomicAdd(&s_out[r], 1);
        int4 d = d4[i];
        r = d.x - lo; if ((unsigned)r < RNODES) atomicAdd(&s_in[r], 1);
        r = d.y - lo; if ((unsigned)r < RNODES) atomicAdd(&s_in[r], 1);
        r = d.z - lo; if ((unsigned)r < RNODES) atomicAdd(&s_in[r], 1);
        r = d.w - lo; if ((unsigned)r < RNODES) atomicAdd(&s_in[r], 1);
    }
    __syncthreads();

    for (int r = threadIdx.x; r < RNODES; r += blockDim.x) {
        int node = lo + r;
        if (node < N_NODES) {
            int di = s_in[r];
            int dو = s_out[r];
            g_indeg[node]   = di;
            g_innorm[node]  = rsqrtf(fmaxf((float)di, 1.0f));
            g_outnorm[node] = rsqrtf(fmaxf((float)dو, 1.0f));
        }
    }
}

// ---------------------------------------------------------------------------
// single-block exclusive scan of g_indeg -> g_rowptr (proven R4/R14 core).
__global__ void k_scan() {
    __shared__ int sdata[1024];
    __shared__ int s_carry;
    int t = threadIdx.x;
    if (t == 0) s_carry = 0;
    __syncthreads();

    for (int base = 0; base < N_NODES; base += 1024) {
        int i = base + t;
        int v = (i < N_NODES) ? g_indeg[i] : 0;
        sdata[t] = v;
        __syncthreads();
        #pragma unroll
        for (int off = 1; off < 1024; off <<= 1) {
            int x = (t >= off) ? sdata[t - off] : 0;
            __syncthreads();
            sdata[t] += x;
            __syncthreads();
        }
        int carry = s_carry;
        int excl  = sdata[t] - v;
        if (i < N_NODES) g_rowptr[i] = carry + excl;
        __syncthreads();
        if (t == 0) s_carry = carry + sdata[1023];
        __syncthreads();
    }
    if (t == 0) g_rowptr[N_NODES] = s_carry;
}

// ---------------------------------------------------------------------------
// CSR fill, atomic-free globally. Block owns nodes [lo, lo+RNODES); smem
// cursors seeded from rowptr; streams dst, writes matching edges' src.
__global__ void __launch_bounds__(512)
k_fillb(const int* __restrict__ src, const int* __restrict__ dst) {
    __shared__ int s_cur[RNODES];
    int lo = blockIdx.x * RNODES;

    for (int r = threadIdx.x; r < RNODES; r += blockDim.x) {
        int node = lo + r;
        s_cur[r] = (node < N_NODES) ? g_rowptr[node] : 0;
    }
    __syncthreads();

    const int4* d4 = (const int4*)dst;
    for (int i = threadIdx.x; i < E4; i += blockDim.x) {
        int4 d = d4[i];
        int e = i * 4;
        int r;
        r = d.x - lo;
        if ((unsigned)r < RNODES && d.x < N_NODES) {
            int p = atomicAdd(&s_cur[r], 1);
            g_csr[p] = src[e + 0];
        }
        r = d.y - lo;
        if ((unsigned)r < RNODES && d.y < N_NODES) {
            int p = atomicAdd(&s_cur[r], 1);
            g_csr[p] = src[e + 1];
        }
        r = d.z - lo;
        if ((unsigned)r < RNODES && d.z < N_NODES) {
            int p = atomicAdd(&s_cur[r], 1);
            g_csr[p] = src[e + 2];
        }
        r = d.w - lo;
        if ((unsigned)r < RNODES && d.w < N_NODES) {
            int p = atomicAdd(&s_cur[r], 1);
            g_csr[p] = src[e + 3];
        }
    }
}

// ---------------------------------------------------------------------------
// Aggregation: one warp per node, x8 unrolled gather (verbatim from R15).
// OUT[v] = relu?( in_norm[v] * sum_e out_norm[s] * Y[s] + bias )
template <bool RELU>
__global__ void k_agg(const float* __restrict__ Y,
                      const float* __restrict__ bias,
                      float* __restrict__ OUT) {
    int node = (blockIdx.x * blockDim.x + threadIdx.x) >> 5;
    if (node >= N_NODES) return;
    int lane = threadIdx.x & 31;

    int beg = g_rowptr[node];
    int end = g_rowptr[node + 1];

    const float4* X4 = (const float4*)Y;
    float4 acc = make_float4(0.f, 0.f, 0.f, 0.f);

    int i = beg;
    for (; i + 8 <= end; i += 8) {
        int s0 = g_csr[i + 0];
        int s1 = g_csr[i + 1];
        int s2 = g_csr[i + 2];
        int s3 = g_csr[i + 3];
        int s4 = g_csr[i + 4];
        int s5 = g_csr[i + 5];
        int s6 = g_csr[i + 6];
        int s7 = g_csr[i + 7];
        float n0 = __ldg(&g_outnorm[s0]);
        float n1 = __ldg(&g_outnorm[s1]);
        float n2 = __ldg(&g_outnorm[s2]);
        float n3 = __ldg(&g_outnorm[s3]);
        float n4 = __ldg(&g_outnorm[s4]);
        float n5 = __ldg(&g_outnorm[s5]);
        float n6 = __ldg(&g_outnorm[s6]);
        float n7 = __ldg(&g_outnorm[s7]);
        float4 a0 = X4[s0 * DV + lane];
        float4 a1 = X4[s1 * DV + lane];
        float4 a2 = X4[s2 * DV + lane];
        float4 a3 = X4[s3 * DV + lane];
        float4 a4 = X4[s4 * DV + lane];
        float4 a5 = X4[s5 * DV + lane];
        float4 a6 = X4[s6 * DV + lane];
        float4 a7 = X4[s7 * DV + lane];
        acc.x += a0.x * n0 + a1.x * n1 + a2.x * n2 + a3.x * n3
               + a4.x * n4 + a5.x * n5 + a6.x * n6 + a7.x * n7;
        acc.y += a0.y * n0 + a1.y * n1 + a2.y * n2 + a3.y * n3
               + a4.y * n4 + a5.y * n5 + a6.y * n6 + a7.y * n7;
        acc.z += a0.z * n0 + a1.z * n1 + a2.z * n2 + a3.z * n3
               + a4.z * n4 + a5.z * n5 + a6.z * n6 + a7.z * n7;
        acc.w += a0.w * n0 + a1.w * n1 + a2.w * n2 + a3.w * n3
               + a4.w * n4 + a5.w * n5 + a6.w * n6 + a7.w * n7;
    }
    for (; i < end; i++) {
        int   s  = g_csr[i];
        float on = __ldg(&g_outnorm[s]);
        float4 xv = X4[s * DV + lane];
        acc.x += xv.x * on;
        acc.y += xv.y * on;
        acc.z += xv.z * on;
        acc.w += xv.w * on;
    }
    float  inn = g_innorm[node];
    float4 bv  = ((const float4*)bias)[lane];
    float4 o;
    o.x = acc.x * inn + bv.x;
    o.y = acc.y * inn + bv.y;
    o.z = acc.z * inn + bv.z;
    o.w = acc.w * inn + bv.w;
    if (RELU) {
        o.x = fmaxf(o.x, 0.f);
        o.y = fmaxf(o.y, 0.f);
        o.z = fmaxf(o.z, 0.f);
        o.w = fmaxf(o.w, 0.f);
    }
    ((float4*)OUT)[node * DV + lane] = o;
}

// ---------------------------------------------------------------------------
// SGEMM: C[M,128] = A[M,128] @ W[128,128]   (verbatim from R15, passing)
__global__ void __launch_bounds__(128)
k_gemm(const float* __restrict__ A, const float* __restrict__ W,
       float* __restrict__ C, int M) {
    __shared__ float As[8][64];
    __shared__ float Bs[8][128];

    int tid = threadIdx.x;
    int blockRow = blockIdx.x;  // tile of 64 rows

    int rowA = tid >> 1;          // 0..63
    int colA = (tid & 1) * 4;     // 0 or 4
    int rowB = tid >> 4;          // 0..7
    int colB = (tid & 15) * 4;    // 0..60  (second chunk at +64)
    int tRow = (tid >> 4) * 8;    // 0..56
    int tCol = (tid & 15) * 8;    // 0..120

    int aRow = blockRow * 64 + rowA;
    bool aValid = (aRow < M);

    float acc[8][8];
    #pragma unroll
    for (int i = 0; i < 8; i++)
        #pragma unroll
        for (int j = 0; j < 8; j++) acc[i][j] = 0.f;

    for (int kc = 0; kc < D; kc += 8) {
        float4 av = aValid ? *(const float4*)(A + (size_t)aRow * D + kc + colA)
                           : make_float4(0.f, 0.f, 0.f, 0.f);
        As[colA + 0][rowA] = av.x;
        As[colA + 1][rowA] = av.y;
        As[colA + 2][rowA] = av.z;
        As[colA + 3][rowA] = av.w;

        *(float4*)&Bs[rowB][colB]      = *(const float4*)(W + (kc + rowB) * D + colB);
        *(float4*)&Bs[rowB][colB + 64] = *(const float4*)(W + (kc + rowB) * D + colB + 64);
        __syncthreads();

        #pragma unroll
        for (int k = 0; k < 8; k++) {
            float regM[8], regN[8];
            float4 m0 = *(const float4*)&As[k][tRow];
            float4 m1 = *(const float4*)&As[k][tRow + 4];
            regM[0] = m0.x; regM[1] = m0.y; regM[2] = m0.z; regM[3] = m0.w;
            regM[4] = m1.x; regM[5] = m1.y; regM[6] = m1.z; regM[7] = m1.w;
            float4 n0 = *(const float4*)&Bs[k][tCol];
            float4 n1 = *(const float4*)&Bs[k][tCol + 4];
            regN[0] = n0.x; regN[1] = n0.y; regN[2] = n0.z; regN[3] = n0.w;
            regN[4] = n1.x; regN[5] = n1.y; regN[6] = n1.z; regN[7] = n1.w;
            #pragma unroll
            for (int i = 0; i < 8; i++)
                #pragma unroll
                for (int j = 0; j < 8; j++)
                    acc[i][j] += regM[i] * regN[j];
        }
        __syncthreads();
    }

    #pragma unroll
    for (int i = 0; i < 8; i++) {
        int r = blockRow * 64 + tRow + i;
        if (r < M) {
            float4 o0 = make_float4(acc[i][0], acc[i][1], acc[i][2], acc[i][3]);
            float4 o1 = make_float4(acc[i][4], acc[i][5], acc[i][6], acc[i][7]);
            *(float4*)(C + (size_t)r * D + tCol)     = o0;
            *(float4*)(C + (size_t)r * D + tCol + 4) = o1;
        }
    }
}

// ---------------------------------------------------------------------------
extern "C" void kernel_launch(void* const* d_in, const int* in_sizes, int n_in,
                              void* d_out, int out_size) {
    const float* x   = (const float*)d_in[0];
    const int*   src = (const int*)d_in[1];   // int32 (JAX x64 disabled)
    const int*   dst = (const int*)d_in[2];
    const float* W1  = (const float*)d_in[3];
    const float* b1  = (const float*)d_in[4];
    const float* W2  = (const float*)d_in[5];
    const float* b2  = (const float*)d_in[6];
    const float* W3  = (const float*)d_in[7];
    const float* b3  = (const float*)d_in[8];
    float* out = (float*)d_out;

    const int aggBlocks  = (N_NODES * 32 + 255) / 256; // 6250 (warp/node)
    const int gemmBlocks = (N_NODES + 63) / 64;        // 782

    // setup: block-private histograms -> scan -> block-private CSR fill
    k_hist<<<NBLK, 512>>>(src, dst);                   // launch 1
    k_scan<<<1, 1024>>>();                             // launch 2
    k_gemm<<<gemmBlocks, 128>>>(x, W1, g_t, N_NODES);  // launch 3 (indep of graph)
    k_fillb<<<NBLK, 512>>>(src, dst);                  // launch 4 <- PROFILED

    // layer 1 epilogue
    k_agg<true><<<aggBlocks, 256>>>(g_t, b1, g_h);     // H1
    // layer 2
    k_gemm<<<gemmBlocks, 128>>>(g_h, W2, g_t, N_NODES);
    k_agg<true><<<aggBlocks, 256>>>(g_t, b2, g_h);     // H2
    // layer 3 (no ReLU) -> d_out
    k_gemm<<<gemmBlocks, 128>>>(g_h, W3, g_t, N_NODES);
    k_agg<false><<<aggBlocks, 256>>>(g_t, b3, out);
}

// round 17
// speedup vs baseline: 1.4462x; 1.4462x over previous
#include <cuda_runtime.h>
#include <cuda_bf16.h>

// RGCN_317827579998 : 3-layer GraphConv, N=50000 nodes, E=800000 edges, D=128.
//
// R17:
//   - agg-first ordering restored (R10/R14 empirically ~2.2ms faster than the
//     GEMM-first R15/R16 despite identical work).
//   - atomic-free setup kept (hist/scan/fillb; fillb measured 194us).
//   - NEW GEMM: 256thr, BM=64/BN=128/BK=8, 8x4 thread tile (~64 regs ->
//     4 blocks/SM = 32 warps vs old 16; A-frag reads are warp-uniform
//     broadcasts). Predicted 378us -> <100us each.
//   layer: T = in_norm .* gather(out_norm .* X) ; H = relu?(T@W + b)
// Launch order: hist(1), scan(2), fillb(3), agg1(4) <- PROFILED (in-context
// re-measure), gemm1, agg2, gemm2, agg3, gemm3->out.

#define N_NODES 50000
#define N_EDGES 800000
#define D 128
#define DV (D / 4)   // float4s per row
#define E4 (N_EDGES / 4)

#define NBLK 148
#define RNODES 338   // 148*338 = 50024 >= N_NODES

// ---- device scratch (allocation-free rules -> __device__ globals) ----
__device__ int   g_indeg[N_NODES];
__device__ float g_outnorm[N_NODES];
__device__ float g_innorm[N_NODES];
__device__ int   g_rowptr[N_NODES + 1];
__device__ int   g_csr[N_EDGES];
__device__ float g_t[N_NODES * D];  // agg output / gemm input
__device__ float g_h[N_NODES * D];  // layer output (gemm output)

// ---------------------------------------------------------------------------
// Histogram + norms. Each block owns nodes [lo, lo+RNODES); streams all edges.
__global__ void __launch_bounds__(512)
k_hist(const int* __restrict__ src, const int* __restrict__ dst) {
    __shared__ int s_in[RNODES];
    __shared__ int s_out[RNODES];
    int lo = blockIdx.x * RNODES;

    for (int r = threadIdx.x; r < RNODES; r += blockDim.x) {
        s_in[r] = 0;
        s_out[r] = 0;
    }
    __syncthreads();

    const int4* s4 = (const int4*)src;
    const int4* d4 = (const int4*)dst;
    for (int i = threadIdx.x; i < E4; i += blockDim.x) {
        int4 s = s4[i];
        int r;
        r = s.x - lo; if ((unsigned)r < RNODES) atomicAdd(&s_out[r], 1);
        r = s.y - lo; if ((unsigned)r < RNODES) atomicAdd(&s_out[r], 1);
        r = s.z - lo; if ((unsigned)r < RNODES) atomicAdd(&s_out[r], 1);
        r = s.w - lo; if ((unsigned)r < RNODES) atomicAdd(&s_out[r], 1);
        int4 d = d4[i];
        r = d.x - lo; if ((unsigned)r < RNODES) atomicAdd(&s_in[r], 1);
        r = d.y - lo; if ((unsigned)r < RNODES) atomicAdd(&s_in[r], 1);
        r = d.z - lo; if ((unsigned)r < RNODES) atomicAdd(&s_in[r], 1);
        r = d.w - lo; if ((unsigned)r < RNODES) atomicAdd(&s_in[r], 1);
    }
    __syncthreads();

    for (int r = threadIdx.x; r < RNODES; r += blockDim.x) {
        int node = lo + r;
        if (node < N_NODES) {
            int di = s_in[r];
            int dn = s_out[r];
            g_indeg[node]   = di;
            g_innorm[node]  = rsqrtf(fmaxf((float)di, 1.0f));
            g_outnorm[node] = rsqrtf(fmaxf((float)dn, 1.0f));
        }
    }
}

// ---------------------------------------------------------------------------
// single-block exclusive scan of g_indeg -> g_rowptr (proven core).
__global__ void k_scan() {
    __shared__ int sdata[1024];
    __shared__ int s_carry;
    int t = threadIdx.x;
    if (t == 0) s_carry = 0;
    __syncthreads();

    for (int base = 0; base < N_NODES; base += 1024) {
        int i = base + t;
        int v = (i < N_NODES) ? g_indeg[i] : 0;
        sdata[t] = v;
        __syncthreads();
        #pragma unroll
        for (int off = 1; off < 1024; off <<= 1) {
            int x = (t >= off) ? sdata[t - off] : 0;
            __syncthreads();
            sdata[t] += x;
            __syncthreads();
        }
        int carry = s_carry;
        int excl  = sdata[t] - v;
        if (i < N_NODES) g_rowptr[i] = carry + excl;
        __syncthreads();
        if (t == 0) s_carry = carry + sdata[1023];
        __syncthreads();
    }
    if (t == 0) g_rowptr[N_NODES] = s_carry;
}

// ---------------------------------------------------------------------------
// CSR fill, no global atomics. Block owns nodes [lo, lo+RNODES); smem cursors
// seeded from rowptr; streams dst, writes matching edges' src.
__global__ void __launch_bounds__(512)
k_fillb(const int* __restrict__ src, const int* __restrict__ dst) {
    __shared__ int s_cur[RNODES];
    int lo = blockIdx.x * RNODES;

    for (int r = threadIdx.x; r < RNODES; r += blockDim.x) {
        int node = lo + r;
        s_cur[r] = (node < N_NODES) ? g_rowptr[node] : 0;
    }
    __syncthreads();

    const int4* d4 = (const int4*)dst;
    for (int i = threadIdx.x; i < E4; i += blockDim.x) {
        int4 d = d4[i];
        int e = i * 4;
        int r;
        r = d.x - lo;
        if ((unsigned)r < RNODES && d.x < N_NODES) {
            int p = atomicAdd(&s_cur[r], 1);
            g_csr[p] = src[e + 0];
        }
        r = d.y - lo;
        if ((unsigned)r < RNODES && d.y < N_NODES) {
            int p = atomicAdd(&s_cur[r], 1);
            g_csr[p] = src[e + 1];
        }
        r = d.z - lo;
        if ((unsigned)r < RNODES && d.z < N_NODES) {
            int p = atomicAdd(&s_cur[r], 1);
            g_csr[p] = src[e + 2];
        }
        r = d.w - lo;
        if ((unsigned)r < RNODES && d.w < N_NODES) {
            int p = atomicAdd(&s_cur[r], 1);
            g_csr[p] = src[e + 3];
        }
    }
}

// ---------------------------------------------------------------------------
// Aggregation: one warp per node, x8 unrolled gather (R10 proven core).
// T[v] = in_norm[v] * sum_e out_norm[s] * X[s]
__global__ void k_agg(const float* __restrict__ X, float* __restrict__ T) {
    int node = (blockIdx.x * blockDim.x + threadIdx.x) >> 5;
    if (node >= N_NODES) return;
    int lane = threadIdx.x & 31;

    int beg = g_rowptr[node];
    int end = g_rowptr[node + 1];

    const float4* X4 = (const float4*)X;
    float4 acc = make_float4(0.f, 0.f, 0.f, 0.f);

    int i = beg;
    for (; i + 8 <= end; i += 8) {
        int s0 = g_csr[i + 0];
        int s1 = g_csr[i + 1];
        int s2 = g_csr[i + 2];
        int s3 = g_csr[i + 3];
        int s4 = g_csr[i + 4];
        int s5 = g_csr[i + 5];
        int s6 = g_csr[i + 6];
        int s7 = g_csr[i + 7];
        float n0 = __ldg(&g_outnorm[s0]);
        float n1 = __ldg(&g_outnorm[s1]);
        float n2 = __ldg(&g_outnorm[s2]);
        float n3 = __ldg(&g_outnorm[s3]);
        float n4 = __ldg(&g_outnorm[s4]);
        float n5 = __ldg(&g_outnorm[s5]);
        float n6 = __ldg(&g_outnorm[s6]);
        float n7 = __ldg(&g_outnorm[s7]);
        float4 a0 = X4[s0 * DV + lane];
        float4 a1 = X4[s1 * DV + lane];
        float4 a2 = X4[s2 * DV + lane];
        float4 a3 = X4[s3 * DV + lane];
        float4 a4 = X4[s4 * DV + lane];
        float4 a5 = X4[s5 * DV + lane];
        float4 a6 = X4[s6 * DV + lane];
        float4 a7 = X4[s7 * DV + lane];
        acc.x += a0.x * n0 + a1.x * n1 + a2.x * n2 + a3.x * n3
               + a4.x * n4 + a5.x * n5 + a6.x * n6 + a7.x * n7;
        acc.y += a0.y * n0 + a1.y * n1 + a2.y * n2 + a3.y * n3
               + a4.y * n4 + a5.y * n5 + a6.y * n6 + a7.y * n7;
        acc.z += a0.z * n0 + a1.z * n1 + a2.z * n2 + a3.z * n3
               + a4.z * n4 + a5.z * n5 + a6.z * n6 + a7.z * n7;
        acc.w += a0.w * n0 + a1.w * n1 + a2.w * n2 + a3.w * n3
               + a4.w * n4 + a5.w * n5 + a6.w * n6 + a7.w * n7;
    }
    for (; i < end; i++) {
        int   s  = g_csr[i];
        float on = __ldg(&g_outnorm[s]);
        float4 xv = X4[s * DV + lane];
        acc.x += xv.x * on;
        acc.y += xv.y * on;
        acc.z += xv.z * on;
        acc.w += xv.w * on;
    }
    float inn = g_innorm[node];
    acc.x *= inn; acc.y *= inn; acc.z *= inn; acc.w *= inn;
    ((float4*)T)[node * DV + lane] = acc;
}

// ---------------------------------------------------------------------------
// NEW SGEMM: C[M,128] = A[M,128] @ W[128,128] + b (+ReLU)
// BM=64, BN=128, BK=8, 256 threads, 8x4 per-thread tile (~64 regs ->
// 4 blocks/SM = 32 warps). A-frag reads are warp-uniform LDS broadcasts.
template <bool RELU>
__global__ void __launch_bounds__(256)
k_gemm(const float* __restrict__ A, const float* __restrict__ W,
       const float* __restrict__ b, float* __restrict__ C, int M) {
    __shared__ float As[8][64];    // [k][row]
    __shared__ float Bs[8][128];   // [k][col]

    int tid  = threadIdx.x;
    int m0   = blockIdx.x * 64;
    int tRow = (tid >> 5) * 8;     // warp id * 8  (0..56)
    int tCol = (tid & 31) * 4;     // lane * 4     (0..124)

    // A staging (first 128 threads): 64 rows x 8 cols = 128 float4s
    int rowA = tid >> 1;           // 0..127 (used only when tid<128 -> 0..63)
    int colA = (tid & 1) * 4;      // 0 or 4
    // B staging (all 256 threads): 8 rows x 128 cols = 256 float4s
    int rowB = tid >> 5;           // 0..7
    int colB = (tid & 31) * 4;     // 0..124

    int  aRow   = m0 + rowA;
    bool aValid = (tid < 128) && (aRow < M);

    float acc[8][4];
    #pragma unroll
    for (int i = 0; i < 8; i++)
        #pragma unroll
        for (int j = 0; j < 4; j++) acc[i][j] = 0.f;

    for (int kc = 0; kc < D; kc += 8) {
        if (tid < 128) {
            float4 av = aValid ? *(const float4*)(A + (size_t)aRow * D + kc + colA)
                               : make_float4(0.f, 0.f, 0.f, 0.f);
            As[colA + 0][rowA] = av.x;
            As[colA + 1][rowA] = av.y;
            As[colA + 2][rowA] = av.z;
            As[colA + 3][rowA] = av.w;
        }
        *(float4*)&Bs[rowB][colB] = *(const float4*)(W + (kc + rowB) * D + colB);
        __syncthreads();

        #pragma unroll
        for (int k = 0; k < 8; k++) {
            float4 m0v = *(const float4*)&As[k][tRow];       // warp-uniform
            float4 m1v = *(const float4*)&As[k][tRow + 4];   // warp-uniform
            float4 nv  = *(const float4*)&Bs[k][tCol];
            float regM[8] = {m0v.x, m0v.y, m0v.z, m0v.w, m1v.x, m1v.y, m1v.z, m1v.w};
            #pragma unroll
            for (int i = 0; i < 8; i++) {
                acc[i][0] += regM[i] * nv.x;
                acc[i][1] += regM[i] * nv.y;
                acc[i][2] += regM[i] * nv.z;
                acc[i][3] += regM[i] * nv.w;
            }
        }
        __syncthreads();
    }

    float4 bv = *(const float4*)(b + tCol);

    #pragma unroll
    for (int i = 0; i < 8; i++) {
        int r = m0 + tRow + i;
        if (r < M) {
            float4 o;
            float v;
            v = acc[i][0] + bv.x; o.x = RELU ? fmaxf(v, 0.f) : v;
            v = acc[i][1] + bv.y; o.y = RELU ? fmaxf(v, 0.f) : v;
            v = acc[i][2] + bv.z; o.z = RELU ? fmaxf(v, 0.f) : v;
            v = acc[i][3] + bv.w; o.w = RELU ? fmaxf(v, 0.f) : v;
            *(float4*)(C + (size_t)r * D + tCol) = o;
        }
    }
}

// ---------------------------------------------------------------------------
extern "C" void kernel_launch(void* const* d_in, const int* in_sizes, int n_in,
                              void* d_out, int out_size) {
    const float* x   = (const float*)d_in[0];
    const int*   src = (const int*)d_in[1];   // int32 (JAX x64 disabled)
    const int*   dst = (const int*)d_in[2];
    const float* W1  = (const float*)d_in[3];
    const float* b1  = (const float*)d_in[4];
    const float* W2  = (const float*)d_in[5];
    const float* b2  = (const float*)d_in[6];
    const float* W3  = (const float*)d_in[7];
    const float* b3  = (const float*)d_in[8];
    float* out = (float*)d_out;

    const int aggBlocks  = (N_NODES * 32 + 255) / 256; // 6250 (warp/node)
    const int gemmBlocks = (N_NODES + 63) / 64;        // 782

    // setup: block-private histograms -> scan -> block-private CSR fill
    k_hist<<<NBLK, 512>>>(src, dst);                   // launch 1
    k_scan<<<1, 1024>>>();                             // launch 2
    k_fillb<<<NBLK, 512>>>(src, dst);                  // launch 3

    // layer 1
    k_agg<<<aggBlocks, 256>>>(x, g_t);                 // launch 4 <- PROFILED
    k_gemm<true><<<gemmBlocks, 256>>>(g_t, W1, b1, g_h, N_NODES);
    // layer 2
    k_agg<<<aggBlocks, 256>>>(g_h, g_t);
    k_gemm<true><<<gemmBlocks, 256>>>(g_t, W2, b2, g_h, N_NODES);
    // layer 3 (no ReLU) -> d_out
    k_agg<<<aggBlocks, 256>>>(g_h, g_t);
    k_gemm<false><<<gemmBlocks, 256>>>(g_t, W3, b3, out, N_NODES);
}